// round 2
// baseline (speedup 1.0000x reference)
#include <cuda_runtime.h>

// Problem constants
#define B_    4
#define T_    2048
#define HID_  2048
#define NH_   16
#define HD_   128
#define M_    (B_ * T_)       // 8192
#define NQKV_ (3 * HID_)      // 6144

// GEMM tiling
#define BKg 16
#define PAD 132               // smem row stride (multiple of 4 for float4 alignment)

// Scratch (device globals; no allocations allowed)
__device__ float g_q[16777216];     // [B, NH, T, HD]
__device__ float g_k[16777216];
__device__ float g_v[16777216];
__device__ float g_attn[16777216];  // [B, T, HID]

// ---------------------------------------------------------------------------
// Shared 128x128x16 fp32 GEMM mainloop: C[row, col] = sum_k A[row,k]*Bm[col,k]
// (both operands K-contiguous, i.e. "NT" layout). 256 threads, 8x8 microtile.
// ---------------------------------------------------------------------------
__device__ __forceinline__ void gemm128(const float* __restrict__ A,
                                        const float* __restrict__ Bm,
                                        int K, int rowBase, int colBase,
                                        float (&acc)[8][8],
                                        float* As, float* Bs)
{
    const int tid = threadIdx.x;
    const int ty  = tid >> 4;         // 0..15
    const int tx  = tid & 15;         // 0..15
    const int lr  = tid >> 2;         // 0..63
    const int lk  = (tid & 3) << 2;   // 0,4,8,12

    for (int k0 = 0; k0 < K; k0 += BKg) {
#pragma unroll
        for (int j = 0; j < 2; ++j) {
            const int r = lr + j * 64;
            float4 va = *reinterpret_cast<const float4*>(A + (size_t)(rowBase + r) * K + k0 + lk);
            As[(lk + 0) * PAD + r] = va.x;
            As[(lk + 1) * PAD + r] = va.y;
            As[(lk + 2) * PAD + r] = va.z;
            As[(lk + 3) * PAD + r] = va.w;
            float4 vb = *reinterpret_cast<const float4*>(Bm + (size_t)(colBase + r) * K + k0 + lk);
            Bs[(lk + 0) * PAD + r] = vb.x;
            Bs[(lk + 1) * PAD + r] = vb.y;
            Bs[(lk + 2) * PAD + r] = vb.z;
            Bs[(lk + 3) * PAD + r] = vb.w;
        }
        __syncthreads();
#pragma unroll
        for (int kk = 0; kk < BKg; ++kk) {
            float4 a0 = *reinterpret_cast<const float4*>(As + kk * PAD + ty * 4);
            float4 a1 = *reinterpret_cast<const float4*>(As + kk * PAD + 64 + ty * 4);
            float4 b0 = *reinterpret_cast<const float4*>(Bs + kk * PAD + tx * 4);
            float4 b1 = *reinterpret_cast<const float4*>(Bs + kk * PAD + 64 + tx * 4);
            float av[8] = {a0.x, a0.y, a0.z, a0.w, a1.x, a1.y, a1.z, a1.w};
            float bv[8] = {b0.x, b0.y, b0.z, b0.w, b1.x, b1.y, b1.z, b1.w};
#pragma unroll
            for (int i = 0; i < 8; ++i)
#pragma unroll
                for (int jj = 0; jj < 8; ++jj)
                    acc[i][jj] += av[i] * bv[jj];
        }
        __syncthreads();
    }
}

// ---------------------------------------------------------------------------
// Kernel 1: QKV projection + fused RoPE + scatter to [B, NH, T, HD]
// C[m, o] = sum_h x[m,h] * w_qkv[o,h]; o = s*2048 + head*128 + d, s in {q,k,v}
// ---------------------------------------------------------------------------
__global__ void qkv_rope_kernel(const float* __restrict__ x,
                                const float* __restrict__ w_qkv,
                                const float* __restrict__ cosb,
                                const float* __restrict__ sinb)
{
    __shared__ float As[BKg * PAD];
    __shared__ float Bs[BKg * PAD];
    float acc[8][8];
#pragma unroll
    for (int i = 0; i < 8; ++i)
#pragma unroll
        for (int j = 0; j < 8; ++j) acc[i][j] = 0.f;

    const int rowBase = blockIdx.y * 128;
    const int colBase = blockIdx.x * 128;
    gemm128(x, w_qkv, HID_, rowBase, colBase, acc, As, Bs);

    const int ty = threadIdx.x >> 4;
    const int tx = threadIdx.x & 15;

#pragma unroll
    for (int jc = 0; jc < 2; ++jc) {
        const int col = colBase + jc * 64 + tx * 4;  // multiple of 4 -> d even
        const int s   = col >> 11;                   // 0=q, 1=k, 2=v
        const int rem = col & 2047;
        const int h   = rem >> 7;
        const int d   = rem & 127;
#pragma unroll
        for (int ic = 0; ic < 2; ++ic)
#pragma unroll
            for (int i = 0; i < 4; ++i) {
                const int m  = rowBase + ic * 64 + ty * 4 + i;
                const int bb = m >> 11;  // / T_
                const int t  = m & 2047;
                const float v0 = acc[ic * 4 + i][jc * 4 + 0];
                const float v1 = acc[ic * 4 + i][jc * 4 + 1];
                const float v2 = acc[ic * 4 + i][jc * 4 + 2];
                const float v3 = acc[ic * 4 + i][jc * 4 + 3];
                const size_t base = ((size_t)(bb * NH_ + h) * T_ + t) * HD_ + d;
                if (s == 2) {
                    float4 o4 = make_float4(v0, v1, v2, v3);
                    *reinterpret_cast<float4*>(g_v + base) = o4;
                } else {
                    const int i0 = d >> 1;
                    const float c0 = cosb[t * 64 + i0];
                    const float s0 = sinb[t * 64 + i0];
                    const float c1 = cosb[t * 64 + i0 + 1];
                    const float s1 = sinb[t * 64 + i0 + 1];
                    float4 o4;
                    o4.x = v0 * c0 - v1 * s0;
                    o4.y = v0 * s0 + v1 * c0;
                    o4.z = v2 * c1 - v3 * s1;
                    o4.w = v2 * s1 + v3 * c1;
                    float* dst = (s == 0) ? g_q : g_k;
                    *reinterpret_cast<float4*>(dst + base) = o4;
                }
            }
    }
}

// ---------------------------------------------------------------------------
// Kernel 2: flash attention, fp32. One CTA = one (b,h) x 64 query rows.
// ---------------------------------------------------------------------------
#define QSTRIDE 132
#define SSTRIDE 65
#define ATTN_SMEM_FLOATS (3 * 64 * QSTRIDE + 64 * SSTRIDE + 3 * 64)
#define ATTN_SMEM_BYTES  (ATTN_SMEM_FLOATS * 4)

__global__ void attn_kernel()
{
    extern __shared__ float sm[];
    float* Qs = sm;                     // [64][132]
    float* Ks = Qs + 64 * QSTRIDE;      // [64][132]
    float* Vs = Ks + 64 * QSTRIDE;      // [64][132]
    float* Ss = Vs + 64 * QSTRIDE;      // [64][65]
    float* mb = Ss + 64 * SSTRIDE;      // row max
    float* lb = mb + 64;                // row sum
    float* ab = lb + 64;                // row alpha

    const int tid = threadIdx.x;
    const int ty = tid >> 4;            // 0..15
    const int tx = tid & 15;            // 0..15
    const int bh = blockIdx.y;
    const int qBase = blockIdx.x * 64;

    const float* __restrict__ Qg = g_q + (size_t)bh * T_ * HD_;
    const float* __restrict__ Kg = g_k + (size_t)bh * T_ * HD_;
    const float* __restrict__ Vg = g_v + (size_t)bh * T_ * HD_;

    const float scale = 0.08838834764831845f;  // 1/sqrt(128)

    // Load Q tile (scaled)
    {
        const int r0 = tid >> 5;             // 0..7
        const int kc = (tid & 31) << 2;      // 0..124
#pragma unroll
        for (int it = 0; it < 8; ++it) {
            const int row = r0 + it * 8;
            float4 v = *reinterpret_cast<const float4*>(Qg + (size_t)(qBase + row) * HD_ + kc);
            Qs[row * QSTRIDE + kc + 0] = v.x * scale;
            Qs[row * QSTRIDE + kc + 1] = v.y * scale;
            Qs[row * QSTRIDE + kc + 2] = v.z * scale;
            Qs[row * QSTRIDE + kc + 3] = v.w * scale;
        }
    }
    if (tid < 64) { mb[tid] = -1e30f; lb[tid] = 0.f; }

    float oa[4][8];
#pragma unroll
    for (int i = 0; i < 4; ++i)
#pragma unroll
        for (int j = 0; j < 8; ++j) oa[i][j] = 0.f;

    for (int n0 = 0; n0 < T_; n0 += 64) {
        __syncthreads();  // prior tile's GEMM2 reads of Vs/Ss done (covers Q load on iter 0)

        // Load K, V tiles
        {
            const int r0 = tid >> 5;
            const int kc = (tid & 31) << 2;
#pragma unroll
            for (int it = 0; it < 8; ++it) {
                const int row = r0 + it * 8;
                float4 kv = *reinterpret_cast<const float4*>(Kg + (size_t)(n0 + row) * HD_ + kc);
                Ks[row * QSTRIDE + kc + 0] = kv.x;
                Ks[row * QSTRIDE + kc + 1] = kv.y;
                Ks[row * QSTRIDE + kc + 2] = kv.z;
                Ks[row * QSTRIDE + kc + 3] = kv.w;
                float4 vv = *reinterpret_cast<const float4*>(Vg + (size_t)(n0 + row) * HD_ + kc);
                Vs[row * QSTRIDE + kc + 0] = vv.x;
                Vs[row * QSTRIDE + kc + 1] = vv.y;
                Vs[row * QSTRIDE + kc + 2] = vv.z;
                Vs[row * QSTRIDE + kc + 3] = vv.w;
            }
        }
        __syncthreads();

        // S = Q @ K^T  (4x4 microtile per thread)
        float sa[4][4];
#pragma unroll
        for (int i = 0; i < 4; ++i)
#pragma unroll
            for (int j = 0; j < 4; ++j) sa[i][j] = 0.f;

#pragma unroll 4
        for (int kd = 0; kd < HD_; ++kd) {
            float qv[4], kv[4];
#pragma unroll
            for (int i = 0; i < 4; ++i) qv[i] = Qs[(4 * ty + i) * QSTRIDE + kd];
#pragma unroll
            for (int j = 0; j < 4; ++j) kv[j] = Ks[(4 * tx + j) * QSTRIDE + kd];
#pragma unroll
            for (int i = 0; i < 4; ++i)
#pragma unroll
                for (int j = 0; j < 4; ++j) sa[i][j] += qv[i] * kv[j];
        }
#pragma unroll
        for (int i = 0; i < 4; ++i)
#pragma unroll
            for (int j = 0; j < 4; ++j)
                Ss[(4 * ty + i) * SSTRIDE + 4 * tx + j] = sa[i][j];
        __syncthreads();

        // Online softmax (one thread per row)
        if (tid < 64) {
            float* row = Ss + tid * SSTRIDE;
            const float mOld = mb[tid];
            float mNew = mOld;
#pragma unroll 8
            for (int c = 0; c < 64; ++c) mNew = fmaxf(mNew, row[c]);
            const float alpha = __expf(mOld - mNew);
            float l = lb[tid] * alpha;
#pragma unroll 8
            for (int c = 0; c < 64; ++c) {
                const float p = __expf(row[c] - mNew);
                row[c] = p;
                l += p;
            }
            mb[tid] = mNew;
            lb[tid] = l;
            ab[tid] = alpha;
        }
        __syncthreads();

        // Rescale accumulators, then O += P @ V
        float al[4];
#pragma unroll
        for (int i = 0; i < 4; ++i) al[i] = ab[4 * ty + i];
#pragma unroll
        for (int i = 0; i < 4; ++i)
#pragma unroll
            for (int j = 0; j < 8; ++j) oa[i][j] *= al[i];

#pragma unroll 4
        for (int kc = 0; kc < 64; ++kc) {
            float pv[4];
#pragma unroll
            for (int i = 0; i < 4; ++i) pv[i] = Ss[(4 * ty + i) * SSTRIDE + kc];
            float4 v0 = *reinterpret_cast<const float4*>(Vs + kc * QSTRIDE + 4 * tx);
            float4 v1 = *reinterpret_cast<const float4*>(Vs + kc * QSTRIDE + 64 + 4 * tx);
#pragma unroll
            for (int i = 0; i < 4; ++i) {
                oa[i][0] += pv[i] * v0.x;
                oa[i][1] += pv[i] * v0.y;
                oa[i][2] += pv[i] * v0.z;
                oa[i][3] += pv[i] * v0.w;
                oa[i][4] += pv[i] * v1.x;
                oa[i][5] += pv[i] * v1.y;
                oa[i][6] += pv[i] * v1.z;
                oa[i][7] += pv[i] * v1.w;
            }
        }
    }

    // Write to g_attn[b, t, h*128 + d]
    const int b = bh / NH_;
    const int h = bh % NH_;
#pragma unroll
    for (int i = 0; i < 4; ++i) {
        const int row = 4 * ty + i;
        const float inv = 1.f / lb[row];
        const int t = qBase + row;
        float* dst = g_attn + ((size_t)(b * T_ + t)) * HID_ + h * HD_;
        float4 o0 = make_float4(oa[i][0] * inv, oa[i][1] * inv, oa[i][2] * inv, oa[i][3] * inv);
        float4 o1 = make_float4(oa[i][4] * inv, oa[i][5] * inv, oa[i][6] * inv, oa[i][7] * inv);
        *reinterpret_cast<float4*>(dst + 4 * tx) = o0;
        *reinterpret_cast<float4*>(dst + 64 + 4 * tx) = o1;
    }
}

// ---------------------------------------------------------------------------
// Kernel 3: output projection + bias
// out[m, o] = sum_h g_attn[m,h] * w_proj[o,h] + b_proj[o]
// ---------------------------------------------------------------------------
__global__ void proj_kernel(const float* __restrict__ w_proj,
                            const float* __restrict__ bias,
                            float* __restrict__ out)
{
    __shared__ float As[BKg * PAD];
    __shared__ float Bs[BKg * PAD];
    float acc[8][8];
#pragma unroll
    for (int i = 0; i < 8; ++i)
#pragma unroll
        for (int j = 0; j < 8; ++j) acc[i][j] = 0.f;

    const int rowBase = blockIdx.y * 128;
    const int colBase = blockIdx.x * 128;
    gemm128(g_attn, w_proj, HID_, rowBase, colBase, acc, As, Bs);

    const int ty = threadIdx.x >> 4;
    const int tx = threadIdx.x & 15;
#pragma unroll
    for (int jc = 0; jc < 2; ++jc) {
        const int col = colBase + jc * 64 + tx * 4;
        const float b0 = bias[col + 0];
        const float b1 = bias[col + 1];
        const float b2 = bias[col + 2];
        const float b3 = bias[col + 3];
#pragma unroll
        for (int ic = 0; ic < 2; ++ic)
#pragma unroll
            for (int i = 0; i < 4; ++i) {
                const int m = rowBase + ic * 64 + ty * 4 + i;
                float4 o4;
                o4.x = acc[ic * 4 + i][jc * 4 + 0] + b0;
                o4.y = acc[ic * 4 + i][jc * 4 + 1] + b1;
                o4.z = acc[ic * 4 + i][jc * 4 + 2] + b2;
                o4.w = acc[ic * 4 + i][jc * 4 + 3] + b3;
                *reinterpret_cast<float4*>(out + (size_t)m * HID_ + col) = o4;
            }
    }
}

// ---------------------------------------------------------------------------
extern "C" void kernel_launch(void* const* d_in, const int* in_sizes, int n_in,
                              void* d_out, int out_size)
{
    const float* x      = (const float*)d_in[0];
    const float* w_qkv  = (const float*)d_in[1];
    const float* w_proj = (const float*)d_in[2];
    const float* b_proj = (const float*)d_in[3];
    const float* cosb   = (const float*)d_in[4];
    const float* sinb   = (const float*)d_in[5];
    float* out = (float*)d_out;

    // 1) QKV GEMM + RoPE scatter
    qkv_rope_kernel<<<dim3(NQKV_ / 128, M_ / 128), 256>>>(x, w_qkv, cosb, sinb);

    // 2) Flash attention
    cudaFuncSetAttribute(attn_kernel, cudaFuncAttributeMaxDynamicSharedMemorySize,
                         ATTN_SMEM_BYTES);
    attn_kernel<<<dim3(T_ / 64, B_ * NH_), 256, ATTN_SMEM_BYTES>>>();

    // 3) Output projection + bias
    proj_kernel<<<dim3(HID_ / 128, M_ / 128), 256>>>(w_proj, b_proj, out);
}